// round 3
// baseline (speedup 1.0000x reference)
#include <cuda_runtime.h>
#include <cstdint>

// Problem constants
#define BATCH   32768
#define IMG     28
#define KPIX    784      // IMG*IMG  (GEMM K dim)
#define OUT_HW  26
#define OPIX    676      // OUT_HW*OUT_HW
#define HID     200
#define HPAD    256      // padded hidden (GEMM N dim)
#define NOUT    10

// GEMM tiling
#define BM      64
#define BN      256
#define BK      8
#define TM      8
#define TN      16
#define NTHREADS 128
#define NKT     (KPIX / BK)   // 98

// Scratch: effective first-layer weight, conv folded in. 256*784 floats = 3.2 MB.
__device__ __align__(16) float g_Weff[HPAD * KPIX];

// ---------------------------------------------------------------------------
// Kernel 1: fold conv into w0.
// Weff[j,p] = sum_{ky,kx} conv_w[ky,kx] * w0[j, (py-ky)*26 + (px-kx)]
// grid = HPAD blocks (one per hidden unit j), block = 784 threads (one per pixel p)
// ---------------------------------------------------------------------------
__global__ void build_weff_kernel(const float* __restrict__ conv_w,
                                  const float* __restrict__ w0) {
    int j = blockIdx.x;      // 0..255
    int p = threadIdx.x;     // 0..783
    float s = 0.0f;
    if (j < HID) {
        int py = p / IMG;
        int px = p % IMG;
        #pragma unroll
        for (int ky = 0; ky < 3; ky++) {
            #pragma unroll
            for (int kx = 0; kx < 3; kx++) {
                int oy = py - ky;
                int ox = px - kx;
                if (oy >= 0 && oy < OUT_HW && ox >= 0 && ox < OUT_HW) {
                    s += conv_w[ky * 3 + kx] * w0[j * OPIX + oy * OUT_HW + ox];
                }
            }
        }
    }
    g_Weff[j * KPIX + p] = s;
}

// ---------------------------------------------------------------------------
// Packed f32x2 helpers (sm_103a)
// ---------------------------------------------------------------------------
__device__ __forceinline__ unsigned long long pack2(float lo, float hi) {
    unsigned long long r;
    asm("mov.b64 %0, {%1, %2};" : "=l"(r) : "f"(lo), "f"(hi));
    return r;
}
__device__ __forceinline__ void fma2(unsigned long long& d,
                                     unsigned long long a,
                                     unsigned long long b) {
    asm("fma.rn.f32x2 %0, %1, %2, %0;" : "+l"(d) : "l"(a), "l"(b));
}
__device__ __forceinline__ float2 unpack2(unsigned long long v) {
    float2 f;
    asm("mov.b64 {%0, %1}, %2;" : "=f"(f.x), "=f"(f.y) : "l"(v));
    return f;
}

// ---------------------------------------------------------------------------
// Kernel 2: fused  out = relu(X @ WeffT + b0) @ w1T + b1
// One CTA: 64 batch rows x all 256 (padded) hidden units.
// 128 threads: ty = tid/16 (M, TM=8 rows), tx = tid%16 (N, TN=16 cols as f32x2 pairs)
// ---------------------------------------------------------------------------
__global__ void __launch_bounds__(NTHREADS)
fused_mlp_kernel(const float* __restrict__ X,
                 const float* __restrict__ b0,
                 const float* __restrict__ w1,
                 const float* __restrict__ b1,
                 float* __restrict__ out) {
    __shared__ __align__(16) float As[2][BK][BM];    //  4 KB
    __shared__ __align__(16) float Ws[2][BK][BN];    // 16 KB
    __shared__ __align__(16) float w1s[NOUT][HPAD];  // 10 KB
    __shared__ float b0s[HPAD];                      //  1 KB

    const int tid = threadIdx.x;
    const int ty  = tid >> 4;   // 0..7
    const int tx  = tid & 15;   // 0..15
    const int m0  = blockIdx.x * BM;

    // --- preload epilogue weights (padded with zeros above HID) ---
    for (int i = tid; i < NOUT * HPAD; i += NTHREADS) {
        int c = i / HPAD;
        int j = i % HPAD;
        w1s[c][j] = (j < HID) ? w1[c * HID + j] : 0.0f;
    }
    for (int i = tid; i < HPAD; i += NTHREADS) {
        b0s[i] = (i < HID) ? b0[i] : 0.0f;
    }

    // --- tile loader: transpose into [k][m] / [k][j] layout ---
    const int row = tid >> 1;          // 0..63
    const int kq  = (tid & 1) * 4;     // 0 or 4

    // load tile kt=0 into buffer 0
    {
        float4 xa = *reinterpret_cast<const float4*>(X + (m0 + row) * KPIX + kq);
        As[0][kq + 0][row] = xa.x; As[0][kq + 1][row] = xa.y;
        As[0][kq + 2][row] = xa.z; As[0][kq + 3][row] = xa.w;
        #pragma unroll
        for (int s = 0; s < 4; s++) {
            int j = row + 64 * s;
            float4 wv = *reinterpret_cast<const float4*>(g_Weff + j * KPIX + kq);
            Ws[0][kq + 0][j] = wv.x; Ws[0][kq + 1][j] = wv.y;
            Ws[0][kq + 2][j] = wv.z; Ws[0][kq + 3][j] = wv.w;
        }
    }
    __syncthreads();

    unsigned long long acc[TM][TN / 2];
    #pragma unroll
    for (int r = 0; r < TM; r++)
        #pragma unroll
        for (int g = 0; g < TN / 2; g++)
            acc[r][g] = 0ULL;

    // --- main K loop, double buffered ---
    int buf = 0;
    for (int kt = 0; kt < NKT; kt++) {
        if (kt + 1 < NKT) {
            int kbase = (kt + 1) * BK + kq;
            float4 xa = *reinterpret_cast<const float4*>(X + (m0 + row) * KPIX + kbase);
            int nb = buf ^ 1;
            As[nb][kq + 0][row] = xa.x; As[nb][kq + 1][row] = xa.y;
            As[nb][kq + 2][row] = xa.z; As[nb][kq + 3][row] = xa.w;
            #pragma unroll
            for (int s = 0; s < 4; s++) {
                int j = row + 64 * s;
                float4 wv = *reinterpret_cast<const float4*>(g_Weff + j * KPIX + kbase);
                Ws[nb][kq + 0][j] = wv.x; Ws[nb][kq + 1][j] = wv.y;
                Ws[nb][kq + 2][j] = wv.z; Ws[nb][kq + 3][j] = wv.w;
            }
        }

        #pragma unroll
        for (int kk = 0; kk < BK; kk++) {
            float4 a0 = *reinterpret_cast<const float4*>(&As[buf][kk][ty * TM]);
            float4 a1 = *reinterpret_cast<const float4*>(&As[buf][kk][ty * TM + 4]);
            unsigned long long ad[TM];
            ad[0] = pack2(a0.x, a0.x); ad[1] = pack2(a0.y, a0.y);
            ad[2] = pack2(a0.z, a0.z); ad[3] = pack2(a0.w, a0.w);
            ad[4] = pack2(a1.x, a1.x); ad[5] = pack2(a1.y, a1.y);
            ad[6] = pack2(a1.z, a1.z); ad[7] = pack2(a1.w, a1.w);

            unsigned long long wv[TN / 2];
            #pragma unroll
            for (int s = 0; s < 4; s++) {
                ulonglong2 t = *reinterpret_cast<const ulonglong2*>(
                    &Ws[buf][kk][tx * 4 + 64 * s]);
                wv[2 * s]     = t.x;
                wv[2 * s + 1] = t.y;
            }

            #pragma unroll
            for (int r = 0; r < TM; r++)
                #pragma unroll
                for (int g = 0; g < TN / 2; g++)
                    fma2(acc[r][g], ad[r], wv[g]);
        }
        __syncthreads();
        buf ^= 1;
    }

    // --- fused epilogue: h = relu(acc + b0); out = h @ w1T + b1 ---
    #pragma unroll
    for (int r = 0; r < TM; r++) {
        float p[NOUT];
        #pragma unroll
        for (int c = 0; c < NOUT; c++) p[c] = 0.0f;

        #pragma unroll
        for (int g = 0; g < TN / 2; g++) {
            int j0 = tx * 4 + 64 * (g >> 1) + 2 * (g & 1);
            float2 av = unpack2(acc[r][g]);
            float h0 = fmaxf(av.x + b0s[j0], 0.0f);
            float h1 = fmaxf(av.y + b0s[j0 + 1], 0.0f);
            #pragma unroll
            for (int c = 0; c < NOUT; c++)
                p[c] += h0 * w1s[c][j0] + h1 * w1s[c][j0 + 1];
        }

        // reduce across the 16 tx lanes (same ty group = contiguous half-warp)
        #pragma unroll
        for (int off = 8; off > 0; off >>= 1) {
            #pragma unroll
            for (int c = 0; c < NOUT; c++)
                p[c] += __shfl_down_sync(0xffffffffu, p[c], off, 16);
        }

        if (tx == 0) {
            int m = m0 + ty * TM + r;
            #pragma unroll
            for (int c = 0; c < NOUT; c++)
                out[m * NOUT + c] = p[c] + b1[c];
        }
    }
}

// ---------------------------------------------------------------------------
// kernel_launch: graph-capturable, allocation-free.
// Inputs (metadata order): x, conv_w, w0, b0, w1, b1
// ---------------------------------------------------------------------------
extern "C" void kernel_launch(void* const* d_in, const int* in_sizes, int n_in,
                              void* d_out, int out_size) {
    const float* x      = (const float*)d_in[0];
    const float* conv_w = (const float*)d_in[1];
    const float* w0     = (const float*)d_in[2];
    const float* b0     = (const float*)d_in[3];
    const float* w1     = (const float*)d_in[4];
    const float* b1     = (const float*)d_in[5];
    float* out = (float*)d_out;

    build_weff_kernel<<<HPAD, KPIX>>>(conv_w, w0);
    fused_mlp_kernel<<<BATCH / BM, NTHREADS>>>(x, b0, w1, b1, out);
}

// round 5
// speedup vs baseline: 2.9564x; 2.9564x over previous
#include <cuda_runtime.h>
#include <cuda_bf16.h>
#include <cstdint>

// ---------------------------------------------------------------------------
// Problem constants
// ---------------------------------------------------------------------------
#define BATCH   32768
#define IMG     28
#define KPIX    784      // GEMM K
#define OUT_HW  26
#define OPIX    676
#define HID     200
#define HPAD    256      // padded hidden (GEMM N)
#define NOUT    10

#define BM      128      // M rows per CTA
#define BK      64       // K per chunk (bf16 -> 128B rows, SW128)
#define NCHUNK  13       // 12*64 + 16
#define GEMM_THREADS 256

// idesc kind::f16 (bf16 in, fp32 acc), M=128, N=256:
//   dtype F32 (1<<4) | atype BF16 (1<<7) | btype BF16 (1<<10)
//   | (N/8)<<17 | (M/16)<<24
#define MMA_IDESC 0x8400490u

// tcgen05 is an arch-SPECIFIC (sm_103a) feature. The harness also builds a
// plain compute_103 pass, which must not see any tcgen05 PTX.
#if defined(__CUDA_ARCH__) && defined(__CUDA_ARCH_FEAT_SM103_ALL)
#define HAS_TCGEN05 1
#else
#define HAS_TCGEN05 0
#endif

// ---------------------------------------------------------------------------
// Global scratch (__device__ arrays are allowed).
//   g_Bhi/g_Blo : pre-swizzled bf16 Weff tiles [chunk][256 x 64, SW128, 32KB]
//   g_Weff      : fp32 Weff for the portable fallback path
// ---------------------------------------------------------------------------
__device__ __align__(16) __nv_bfloat16 g_Bhi[NCHUNK * HPAD * BK];
__device__ __align__(16) __nv_bfloat16 g_Blo[NCHUNK * HPAD * BK];
__device__ __align__(16) float         g_Weff[HPAD * KPIX];

// ---------------------------------------------------------------------------
// Arch-neutral helpers
// ---------------------------------------------------------------------------
__device__ __forceinline__ uint32_t smem_to_u32(const void* p) {
    uint32_t a;
    asm("{ .reg .u64 t; cvta.to.shared.u64 t, %1; cvt.u32.u64 %0, t; }"
        : "=r"(a) : "l"(p));
    return a;
}
__device__ __forceinline__ unsigned long long pack2(float lo, float hi) {
    unsigned long long r;
    asm("mov.b64 %0, {%1, %2};" : "=l"(r) : "f"(lo), "f"(hi));
    return r;
}
__device__ __forceinline__ void fma2(unsigned long long& d,
                                     unsigned long long a,
                                     unsigned long long b) {
    asm("fma.rn.f32x2 %0, %1, %2, %0;" : "+l"(d) : "l"(a), "l"(b));
}
__device__ __forceinline__ float2 unpack2(unsigned long long v) {
    float2 f;
    asm("mov.b64 {%0, %1}, %2;" : "=f"(f.x), "=f"(f.y) : "l"(v));
    return f;
}

#if HAS_TCGEN05
// ---------------------------------------------------------------------------
// tcgen05 / mbarrier PTX helpers (sm_103a-only compilation)
// ---------------------------------------------------------------------------
__device__ __forceinline__ uint32_t elect_one_pred() {
    uint32_t pred;
    asm volatile(
        "{\n\t.reg .pred p;\n\t"
        "elect.sync _|p, 0xFFFFFFFF;\n\t"
        "selp.b32 %0, 1, 0, p;\n\t}"
        : "=r"(pred));
    return pred;
}

#define MBARRIER_INIT(addr, cnt) \
    asm volatile("mbarrier.init.shared.b64 [%0], %1;" \
        :: "r"((uint32_t)(addr)), "r"((uint32_t)(cnt)) : "memory")

#define MBARRIER_WAIT_PARITY(addr, par) do { \
    uint32_t _m = (uint32_t)(addr); \
    uint32_t _p = (uint32_t)(par); \
    uint32_t _done; \
    asm volatile( \
        "{\n\t.reg .pred p;\n\t" \
        "mbarrier.try_wait.parity.acquire.cta.shared::cta.b64 p, [%1], %2;\n\t" \
        "selp.b32 %0, 1, 0, p;\n\t}" \
        : "=r"(_done) : "r"(_m), "r"(_p) : "memory"); \
    if (!_done) { \
        asm volatile( \
            "{\n\t.reg .pred P1;\n\t" \
            "WAIT_LOOP_%=:\n\t" \
            "mbarrier.try_wait.parity.acquire.cta.shared::cta.b64 P1, [%0], %1, 0x989680;\n\t" \
            "@P1 bra.uni WAIT_DONE_%=;\n\t" \
            "bra.uni WAIT_LOOP_%=;\n\t" \
            "WAIT_DONE_%=:\n\t}" \
            :: "r"(_m), "r"(_p) : "memory"); \
    } \
} while (0)

#define TCGEN05_ALLOC(res_addr, ncols) \
    asm volatile("tcgen05.alloc.cta_group::1.sync.aligned.shared::cta.b32 [%0], %1;" \
        :: "r"((uint32_t)(res_addr)), "r"((uint32_t)(ncols)) : "memory")
#define TCGEN05_DEALLOC(tmem, ncols) \
    asm volatile("tcgen05.dealloc.cta_group::1.sync.aligned.b32 %0, %1;" \
        :: "r"(tmem), "r"((uint32_t)(ncols)))
#define TCGEN05_RELINQUISH() \
    asm volatile("tcgen05.relinquish_alloc_permit.cta_group::1.sync.aligned;")
#define TCGEN05_COMMIT(mbar) \
    asm volatile("tcgen05.commit.cta_group::1.mbarrier::arrive::one.shared::cluster.b64 [%0];" \
        :: "r"((uint32_t)(mbar)) : "memory")
#define TCGEN05_WAIT_LD() \
    asm volatile("tcgen05.wait::ld.sync.aligned;" ::: "memory")
#define TCGEN05_FENCE_BEFORE() \
    asm volatile("tcgen05.fence::before_thread_sync;" ::: "memory")
#define TCGEN05_FENCE_AFTER() \
    asm volatile("tcgen05.fence::after_thread_sync;" ::: "memory")
#define FENCE_PROXY_ASYNC() \
    asm volatile("fence.proxy.async.shared::cta;" ::: "memory")

#define TCGEN05_LD_32X32B_X32(r, tmem_addr) \
    asm volatile( \
        "tcgen05.ld.sync.aligned.32x32b.x32.b32 " \
        "{%0, %1, %2, %3, %4, %5, %6, %7, " \
        " %8, %9, %10, %11, %12, %13, %14, %15, " \
        " %16, %17, %18, %19, %20, %21, %22, %23, " \
        " %24, %25, %26, %27, %28, %29, %30, %31}, [%32];" \
        : "=r"((r)[0]),  "=r"((r)[1]),  "=r"((r)[2]),  "=r"((r)[3]), \
          "=r"((r)[4]),  "=r"((r)[5]),  "=r"((r)[6]),  "=r"((r)[7]), \
          "=r"((r)[8]),  "=r"((r)[9]),  "=r"((r)[10]), "=r"((r)[11]), \
          "=r"((r)[12]), "=r"((r)[13]), "=r"((r)[14]), "=r"((r)[15]), \
          "=r"((r)[16]), "=r"((r)[17]), "=r"((r)[18]), "=r"((r)[19]), \
          "=r"((r)[20]), "=r"((r)[21]), "=r"((r)[22]), "=r"((r)[23]), \
          "=r"((r)[24]), "=r"((r)[25]), "=r"((r)[26]), "=r"((r)[27]), \
          "=r"((r)[28]), "=r"((r)[29]), "=r"((r)[30]), "=r"((r)[31]) \
        : "r"(tmem_addr))

// SW128 K-major descriptor base (LBO=1, SBO=64, version=1, layout=SW128)
static constexpr uint64_t SMEM_DESC_BASE_SW128 =
    (uint64_t(2)  << 61) | (uint64_t(1) << 46) |
    (uint64_t(64) << 32) | (uint64_t(1) << 16);
#define MAKE_SMEM_DESC(addr) \
    (SMEM_DESC_BASE_SW128 | ((uint64_t)((addr) >> 4) & 0x3FFF))

__device__ __forceinline__ void mma_f16_ss(uint32_t d_tmem, uint64_t a_desc,
                                           uint64_t b_desc, uint32_t idesc,
                                           bool acc) {
    uint32_t en = acc ? 1u : 0u;
    asm volatile(
        "{\n\t.reg .pred p;\n\t"
        "setp.ne.u32 p, %5, 0;\n\t"
        "tcgen05.mma.cta_group::1.kind::f16 [%0], %1, %2, %3, "
        "{%4, %4, %4, %4}, p;\n\t}"
        :: "r"(d_tmem), "l"(a_desc), "l"(b_desc), "r"(idesc),
           "r"(0u), "r"(en)
        : "memory");
}
#endif // HAS_TCGEN05

// ---------------------------------------------------------------------------
// Kernel 1: fold conv into w0. Writes fp32 g_Weff (fallback) AND pre-swizzled
// bf16 hi/lo tiles (tcgen05 path). grid=HPAD, block=832 (13 chunks * 64)
// ---------------------------------------------------------------------------
__global__ void build_weff_kernel(const float* __restrict__ conv_w,
                                  const float* __restrict__ w0) {
    int j = blockIdx.x;      // hidden unit 0..255
    int p = threadIdx.x;     // k position 0..831
    float s = 0.0f;
    if (j < HID && p < KPIX) {
        int py = p / IMG, px = p % IMG;
        #pragma unroll
        for (int ky = 0; ky < 3; ky++)
            #pragma unroll
            for (int kx = 0; kx < 3; kx++) {
                int oy = py - ky, ox = px - kx;
                if (oy >= 0 && oy < OUT_HW && ox >= 0 && ox < OUT_HW)
                    s += conv_w[ky * 3 + kx] * w0[j * OPIX + oy * OUT_HW + ox];
            }
    }
    if (p < KPIX) g_Weff[j * KPIX + p] = s;

    __nv_bfloat16 hi = __float2bfloat16_rn(s);
    __nv_bfloat16 lo = __float2bfloat16_rn(s - __bfloat162float(hi));
    int chunk = p >> 6, kin = p & 63;
    uint32_t off = (uint32_t)(j * 128 + kin * 2);      // bytes within 32KB tile
    uint32_t sw  = off ^ ((off >> 3) & 0x70);          // SW128
    int idx = chunk * (HPAD * BK) + (int)(sw >> 1);
    g_Bhi[idx] = hi;
    g_Blo[idx] = lo;
}

// ---------------------------------------------------------------------------
// Kernel 2: fused  out = relu(X @ WeffT + b0) @ w1T + b1
// sm_103a body: tcgen05 bf16 2-way split (hi*hi + hi*lo + lo*hi, fp32 TMEM).
// Portable body: plain SIMT (compiles everywhere; never selected at runtime).
// ---------------------------------------------------------------------------
// smem byte offsets (dynamic smem, tiles 1024-aligned)
#define SM_CTRL   0          // tmem ptr @0, mbar0 @16, mbar1 @24
#define SM_AHI    1024       // 2 x 16KB
#define SM_ALO    33792      // 2 x 16KB
#define SM_BHI    66560      // 2 x 32KB
#define SM_BLO    132096     // 2 x 32KB
#define SM_W1P    197632     // 256*5*8 = 10240
#define SM_B0     207872     // 1024
#define SM_OUT    208896     // 128*10*4 = 5120
#define SMEM_TOTAL 214016

__global__ void __launch_bounds__(GEMM_THREADS, 1)
gemm_fused_kernel(const float* __restrict__ X,
                  const float* __restrict__ b0,
                  const float* __restrict__ w1,
                  const float* __restrict__ b1,
                  float* __restrict__ out) {
#if HAS_TCGEN05
    extern __shared__ char smem[];
    const uint32_t smem_base = smem_to_u32(smem);
    const int tid = threadIdx.x;
    const int wid = tid >> 5;
    const int lid = tid & 31;
    const int m0  = blockIdx.x * BM;

    // TMEM alloc (warp 0, collective): 256 fp32 accumulator columns
    if (wid == 0) TCGEN05_ALLOC(smem_base + SM_CTRL, 256);

    // epilogue weights into smem (w1 packed as f32x2 pairs) + mbarrier init
    if (tid < HPAD) {
        int j = tid;
        float* b0s = (float*)(smem + SM_B0);
        b0s[j] = (j < HID) ? b0[j] : 0.0f;
        unsigned long long* w1p = (unsigned long long*)(smem + SM_W1P);
        #pragma unroll
        for (int cc = 0; cc < 5; cc++) {
            float a  = (j < HID) ? w1[(2 * cc) * HID + j] : 0.0f;
            float bb = (j < HID) ? w1[(2 * cc + 1) * HID + j] : 0.0f;
            w1p[j * 5 + cc] = pack2(a, bb);
        }
    }
    if (tid == 0) {
        MBARRIER_INIT(smem_base + SM_CTRL + 16, 1);
        MBARRIER_INIT(smem_base + SM_CTRL + 24, 1);
    }
    __syncthreads();

    uint32_t tmem;
    asm volatile("ld.shared.b32 %0, [%1];" : "=r"(tmem) : "r"(smem_base + SM_CTRL));

    // ---- chunk loader: B = straight 32KB copies (pre-swizzled),
    //                    A = fp32 load -> bf16 hi/lo split -> swizzled STS ----
    auto load_chunk = [&](int c, int b) {
        {
            const uint4* shi = (const uint4*)(g_Bhi + c * (HPAD * BK));
            const uint4* slo = (const uint4*)(g_Blo + c * (HPAD * BK));
            uint4* dhi = (uint4*)(smem + SM_BHI + b * 32768);
            uint4* dlo = (uint4*)(smem + SM_BLO + b * 32768);
            #pragma unroll
            for (int i = 0; i < 8; i++) {
                dhi[tid + 256 * i] = shi[tid + 256 * i];
                dlo[tid + 256 * i] = slo[tid + 256 * i];
            }
        }
        {
            int r  = tid >> 1;             // 0..127
            int cb = (tid & 1) * 32;       // 0 or 32
            const float* xp = X + (long)(m0 + r) * KPIX + c * BK + cb;
            char* ahi = smem + SM_AHI + b * 16384;
            char* alo = smem + SM_ALO + b * 16384;
            #pragma unroll
            for (int i = 0; i < 8; i++) {
                int col = cb + i * 4;
                if (c * BK + col < KPIX) {
                    float4 v = *(const float4*)(xp + i * 4);
                    __nv_bfloat16 h0 = __float2bfloat16_rn(v.x);
                    __nv_bfloat16 h1 = __float2bfloat16_rn(v.y);
                    __nv_bfloat16 h2 = __float2bfloat16_rn(v.z);
                    __nv_bfloat16 h3 = __float2bfloat16_rn(v.w);
                    __nv_bfloat16 l0 = __float2bfloat16_rn(v.x - __bfloat162float(h0));
                    __nv_bfloat16 l1 = __float2bfloat16_rn(v.y - __bfloat162float(h1));
                    __nv_bfloat16 l2 = __float2bfloat16_rn(v.z - __bfloat162float(h2));
                    __nv_bfloat16 l3 = __float2bfloat16_rn(v.w - __bfloat162float(h3));
                    __nv_bfloat162 hp0{h0, h1}, hp1{h2, h3};
                    __nv_bfloat162 lp0{l0, l1}, lp1{l2, l3};
                    uint2 hv, lv;
                    hv.x = *(uint32_t*)&hp0; hv.y = *(uint32_t*)&hp1;
                    lv.x = *(uint32_t*)&lp0; lv.y = *(uint32_t*)&lp1;
                    uint32_t off = (uint32_t)(r * 128 + col * 2);
                    uint32_t sw  = off ^ ((off >> 3) & 0x70);
                    *(uint2*)(ahi + sw) = hv;
                    *(uint2*)(alo + sw) = lv;
                }
            }
        }
    };

    // prologue: load chunk 0 into buffer 0
    load_chunk(0, 0);
    FENCE_PROXY_ASYNC();
    __syncthreads();

    // ---- main K loop: double buffered, MMA completion via commit/mbarrier ----
    int ph0 = 0, ph1 = 0;
    for (int c = 0; c < NCHUNK; c++) {
        const int b = c & 1;

        if (wid == 0) {
            if (elect_one_pred()) {
                TCGEN05_FENCE_AFTER();
                uint64_t ah = MAKE_SMEM_DESC(smem_base + SM_AHI + b * 16384);
                uint64_t al = MAKE_SMEM_DESC(smem_base + SM_ALO + b * 16384);
                uint64_t bh = MAKE_SMEM_DESC(smem_base + SM_BHI + b * 32768);
                uint64_t bl = MAKE_SMEM_DESC(smem_base + SM_BLO + b * 32768);
                int nst = (c == NCHUNK - 1) ? 1 : 4;   // K=16 per MMA step
                for (int ks = 0; ks < nst; ks++) {
                    uint64_t o = (uint64_t)(ks * 2);   // +32B per 16 bf16
                    mma_f16_ss(tmem, ah + o, bh + o, MMA_IDESC, !(c == 0 && ks == 0));
                    mma_f16_ss(tmem, ah + o, bl + o, MMA_IDESC, true);
                    mma_f16_ss(tmem, al + o, bh + o, MMA_IDESC, true);
                }
                TCGEN05_COMMIT(smem_base + SM_CTRL + 16 + 8 * b);
            }
        }

        if (c + 1 < NCHUNK) load_chunk(c + 1, b ^ 1);

        // wait chunk c MMAs complete -> buffer b reusable, results ordered
        if (b == 0) { MBARRIER_WAIT_PARITY(smem_base + SM_CTRL + 16, ph0); ph0 ^= 1; }
        else        { MBARRIER_WAIT_PARITY(smem_base + SM_CTRL + 24, ph1); ph1 ^= 1; }
        FENCE_PROXY_ASYNC();
        __syncthreads();
    }

    // ---- fused epilogue: h = relu(D + b0); out = h @ w1T + b1 ----
    TCGEN05_FENCE_AFTER();
    const int sub  = wid & 3;          // TMEM subpartition (rows sub*32..+31)
    const int half = wid >> 2;         // 0: cols 0..127, 1: cols 128..255
    const int r    = sub * 32 + lid;
    const float* b0s = (const float*)(smem + SM_B0);
    const unsigned long long* w1p = (const unsigned long long*)(smem + SM_W1P);

    unsigned long long p2[5] = {0, 0, 0, 0, 0};
    #pragma unroll
    for (int blk = 0; blk < 4; blk++) {
        uint32_t d[32];
        TCGEN05_LD_32X32B_X32(d, tmem + half * 128 + blk * 32);
        TCGEN05_WAIT_LD();
        #pragma unroll
        for (int i = 0; i < 32; i++) {
            int j = half * 128 + blk * 32 + i;
            float h = fmaxf(__uint_as_float(d[i]) + b0s[j], 0.0f);
            unsigned long long hh = pack2(h, h);
            #pragma unroll
            for (int cc = 0; cc < 5; cc++) fma2(p2[cc], hh, w1p[j * 5 + cc]);
        }
    }
    TCGEN05_FENCE_BEFORE();

    float* outst = (float*)(smem + SM_OUT);
    if (half == 0) {
        #pragma unroll
        for (int cc = 0; cc < 5; cc++) {
            float2 f = unpack2(p2[cc]);
            outst[r * 10 + 2 * cc]     = f.x;
            outst[r * 10 + 2 * cc + 1] = f.y;
        }
    }
    __syncthreads();
    if (half == 1) {
        long m = m0 + r;
        #pragma unroll
        for (int cc = 0; cc < 5; cc++) {
            float2 f = unpack2(p2[cc]);
            out[m * NOUT + 2 * cc]     = outst[r * 10 + 2 * cc]     + f.x + b1[2 * cc];
            out[m * NOUT + 2 * cc + 1] = outst[r * 10 + 2 * cc + 1] + f.y + b1[2 * cc + 1];
        }
    }
    __syncthreads();

    if (wid == 0) {
        TCGEN05_RELINQUISH();
        TCGEN05_DEALLOC(tmem, 256);
    }

#else  // ---------------- portable fallback (non-sm_103a passes) ------------
    extern __shared__ char smem[];
    const int tid  = threadIdx.x;
    const int r    = tid & 127;
    const int half = tid >> 7;
    const int m0   = blockIdx.x * BM;
    float* hbuf = (float*)smem;   // 128 rows x 200 h-values (100 KB)

    const float* xr = X + (long)(m0 + r) * KPIX;
    for (int j = half * 100; j < half * 100 + 100; j++) {
        const float* wr = g_Weff + j * KPIX;
        float s = 0.0f;
        for (int k = 0; k < KPIX; k += 4) {
            float4 xv = *(const float4*)(xr + k);
            float4 wv = *(const float4*)(wr + k);
            s += xv.x * wv.x + xv.y * wv.y + xv.z * wv.z + xv.w * wv.w;
        }
        hbuf[r * HID + j] = fmaxf(s + b0[j], 0.0f);
    }
    __syncthreads();
    if (half == 0) {
        float o[NOUT];
        #pragma unroll
        for (int c = 0; c < NOUT; c++) o[c] = b1[c];
        for (int j = 0; j < HID; j++) {
            float h = hbuf[r * HID + j];
            #pragma unroll
            for (int c = 0; c < NOUT; c++) o[c] += h * w1[c * HID + j];
        }
        #pragma unroll
        for (int c = 0; c < NOUT; c++) out[(long)(m0 + r) * NOUT + c] = o[c];
    }
#endif
}

// ---------------------------------------------------------------------------
// kernel_launch: graph-capturable, allocation-free.
// Inputs (metadata order): x, conv_w, w0, b0, w1, b1
// ---------------------------------------------------------------------------
extern "C" void kernel_launch(void* const* d_in, const int* in_sizes, int n_in,
                              void* d_out, int out_size) {
    const float* x      = (const float*)d_in[0];
    const float* conv_w = (const float*)d_in[1];
    const float* w0     = (const float*)d_in[2];
    const float* b0     = (const float*)d_in[3];
    const float* w1     = (const float*)d_in[4];
    const float* b1     = (const float*)d_in[5];
    float* out = (float*)d_out;

    cudaFuncSetAttribute(gemm_fused_kernel,
                         cudaFuncAttributeMaxDynamicSharedMemorySize, SMEM_TOTAL);

    build_weff_kernel<<<HPAD, NCHUNK * BK>>>(conv_w, w0);
    gemm_fused_kernel<<<BATCH / BM, GEMM_THREADS, SMEM_TOTAL>>>(x, b0, w1, b1, out);
}

// round 6
// speedup vs baseline: 3.1684x; 1.0717x over previous
#include <cuda_runtime.h>
#include <cuda_bf16.h>
#include <cstdint>

// ---------------------------------------------------------------------------
// Problem constants
// ---------------------------------------------------------------------------
#define BATCH   32768
#define IMG     28
#define KPIX    784      // GEMM K
#define OUT_HW  26
#define OPIX    676
#define HID     200
#define HPAD    256      // padded hidden (GEMM N)
#define NOUT    10

#define BM      128      // M rows per CTA
#define BK      64       // K per chunk (bf16 -> 128B rows, SW128)
#define NCHUNK  13       // 12*64 + 16
#define GEMM_THREADS 256
#define NLOAD   224      // loader threads (warps 1..7)

// idesc kind::f16 (bf16 in, fp32 acc), M=128, N=256
#define MMA_IDESC 0x8400490u

#if defined(__CUDA_ARCH__) && defined(__CUDA_ARCH_FEAT_SM103_ALL)
#define HAS_TCGEN05 1
#else
#define HAS_TCGEN05 0
#endif

// ---------------------------------------------------------------------------
// Global scratch.
//  g_B   : per chunk, 64KB contiguous block = [hi 32KB | lo 32KB], SW128
//          pre-swizzled -> one cp.async.bulk per chunk
//  g_Weff: fp32 Weff for the portable fallback path (never runs on GB300)
// ---------------------------------------------------------------------------
__device__ __align__(16) __nv_bfloat16 g_B[NCHUNK * 2 * HPAD * BK];
__device__ __align__(16) float         g_Weff[HPAD * KPIX];

// ---------------------------------------------------------------------------
// Arch-neutral helpers
// ---------------------------------------------------------------------------
__device__ __forceinline__ uint32_t smem_to_u32(const void* p) {
    uint32_t a;
    asm("{ .reg .u64 t; cvta.to.shared.u64 t, %1; cvt.u32.u64 %0, t; }"
        : "=r"(a) : "l"(p));
    return a;
}
__device__ __forceinline__ unsigned long long pack2(float lo, float hi) {
    unsigned long long r;
    asm("mov.b64 %0, {%1, %2};" : "=l"(r) : "f"(lo), "f"(hi));
    return r;
}
__device__ __forceinline__ void fma2(unsigned long long& d,
                                     unsigned long long a,
                                     unsigned long long b) {
    asm("fma.rn.f32x2 %0, %1, %2, %0;" : "+l"(d) : "l"(a), "l"(b));
}
__device__ __forceinline__ float2 unpack2(unsigned long long v) {
    float2 f;
    asm("mov.b64 {%0, %1}, %2;" : "=f"(f.x), "=f"(f.y) : "l"(v));
    return f;
}

#if HAS_TCGEN05
// ---------------------------------------------------------------------------
// tcgen05 / mbarrier / bulk-copy PTX helpers (sm_103a-only compilation)
// ---------------------------------------------------------------------------
__device__ __forceinline__ uint32_t elect_one_pred() {
    uint32_t pred;
    asm volatile(
        "{\n\t.reg .pred p;\n\t"
        "elect.sync _|p, 0xFFFFFFFF;\n\t"
        "selp.b32 %0, 1, 0, p;\n\t}"
        : "=r"(pred));
    return pred;
}

#define MBARRIER_INIT(addr, cnt) \
    asm volatile("mbarrier.init.shared.b64 [%0], %1;" \
        :: "r"((uint32_t)(addr)), "r"((uint32_t)(cnt)) : "memory")

#define MBARRIER_ARRIVE(addr) \
    asm volatile("mbarrier.arrive.release.cta.shared::cta.b64 _, [%0];" \
        :: "r"((uint32_t)(addr)) : "memory")

#define MBARRIER_EXPECT_TX(addr, bytes) \
    asm volatile("mbarrier.arrive.expect_tx.shared.b64 _, [%0], %1;" \
        :: "r"((uint32_t)(addr)), "r"((uint32_t)(bytes)) : "memory")

#define MBARRIER_WAIT_PARITY(addr, par) do { \
    uint32_t _m = (uint32_t)(addr); \
    uint32_t _p = (uint32_t)(par); \
    uint32_t _done; \
    asm volatile( \
        "{\n\t.reg .pred p;\n\t" \
        "mbarrier.try_wait.parity.acquire.cta.shared::cta.b64 p, [%1], %2;\n\t" \
        "selp.b32 %0, 1, 0, p;\n\t}" \
        : "=r"(_done) : "r"(_m), "r"(_p) : "memory"); \
    if (!_done) { \
        asm volatile( \
            "{\n\t.reg .pred P1;\n\t" \
            "WAIT_LOOP_%=:\n\t" \
            "mbarrier.try_wait.parity.acquire.cta.shared::cta.b64 P1, [%0], %1, 0x989680;\n\t" \
            "@P1 bra.uni WAIT_DONE_%=;\n\t" \
            "bra.uni WAIT_LOOP_%=;\n\t" \
            "WAIT_DONE_%=:\n\t}" \
            :: "r"(_m), "r"(_p) : "memory"); \
    } \
} while (0)

// plain bulk copy gmem -> smem, completion via tx mbarrier (UBLKCP)
#define CP_ASYNC_BULK_G2S(dst, src, bytes, mbar) \
    asm volatile( \
        "cp.async.bulk.shared::cluster.global.mbarrier::complete_tx::bytes " \
        "[%0], [%1], %2, [%3];" \
        :: "r"((uint32_t)(dst)), "l"(src), "r"((uint32_t)(bytes)), \
           "r"((uint32_t)(mbar)) : "memory")

#define TCGEN05_ALLOC(res_addr, ncols) \
    asm volatile("tcgen05.alloc.cta_group::1.sync.aligned.shared::cta.b32 [%0], %1;" \
        :: "r"((uint32_t)(res_addr)), "r"((uint32_t)(ncols)) : "memory")
#define TCGEN05_DEALLOC(tmem, ncols) \
    asm volatile("tcgen05.dealloc.cta_group::1.sync.aligned.b32 %0, %1;" \
        :: "r"(tmem), "r"((uint32_t)(ncols)))
#define TCGEN05_RELINQUISH() \
    asm volatile("tcgen05.relinquish_alloc_permit.cta_group::1.sync.aligned;")
#define TCGEN05_COMMIT(mbar) \
    asm volatile("tcgen05.commit.cta_group::1.mbarrier::arrive::one.shared::cluster.b64 [%0];" \
        :: "r"((uint32_t)(mbar)) : "memory")
#define TCGEN05_WAIT_LD() \
    asm volatile("tcgen05.wait::ld.sync.aligned;" ::: "memory")
#define TCGEN05_FENCE_BEFORE() \
    asm volatile("tcgen05.fence::before_thread_sync;" ::: "memory")
#define TCGEN05_FENCE_AFTER() \
    asm volatile("tcgen05.fence::after_thread_sync;" ::: "memory")
#define FENCE_PROXY_ASYNC() \
    asm volatile("fence.proxy.async.shared::cta;" ::: "memory")

#define TCGEN05_LD_32X32B_X32(r, tmem_addr) \
    asm volatile( \
        "tcgen05.ld.sync.aligned.32x32b.x32.b32 " \
        "{%0, %1, %2, %3, %4, %5, %6, %7, " \
        " %8, %9, %10, %11, %12, %13, %14, %15, " \
        " %16, %17, %18, %19, %20, %21, %22, %23, " \
        " %24, %25, %26, %27, %28, %29, %30, %31}, [%32];" \
        : "=r"((r)[0]),  "=r"((r)[1]),  "=r"((r)[2]),  "=r"((r)[3]), \
          "=r"((r)[4]),  "=r"((r)[5]),  "=r"((r)[6]),  "=r"((r)[7]), \
          "=r"((r)[8]),  "=r"((r)[9]),  "=r"((r)[10]), "=r"((r)[11]), \
          "=r"((r)[12]), "=r"((r)[13]), "=r"((r)[14]), "=r"((r)[15]), \
          "=r"((r)[16]), "=r"((r)[17]), "=r"((r)[18]), "=r"((r)[19]), \
          "=r"((r)[20]), "=r"((r)[21]), "=r"((r)[22]), "=r"((r)[23]), \
          "=r"((r)[24]), "=r"((r)[25]), "=r"((r)[26]), "=r"((r)[27]), \
          "=r"((r)[28]), "=r"((r)[29]), "=r"((r)[30]), "=r"((r)[31]) \
        : "r"(tmem_addr))

// SW128 K-major descriptor base (LBO=1, SBO=64, version=1, layout=SW128)
static constexpr uint64_t SMEM_DESC_BASE_SW128 =
    (uint64_t(2)  << 61) | (uint64_t(1) << 46) |
    (uint64_t(64) << 32) | (uint64_t(1) << 16);
#define MAKE_SMEM_DESC(addr) \
    (SMEM_DESC_BASE_SW128 | ((uint64_t)((addr) >> 4) & 0x3FFF))

__device__ __forceinline__ void mma_f16_ss(uint32_t d_tmem, uint64_t a_desc,
                                           uint64_t b_desc, uint32_t idesc,
                                           bool acc) {
    uint32_t en = acc ? 1u : 0u;
    asm volatile(
        "{\n\t.reg .pred p;\n\t"
        "setp.ne.u32 p, %5, 0;\n\t"
        "tcgen05.mma.cta_group::1.kind::f16 [%0], %1, %2, %3, "
        "{%4, %4, %4, %4}, p;\n\t}"
        :: "r"(d_tmem), "l"(a_desc), "l"(b_desc), "r"(idesc),
           "r"(0u), "r"(en)
        : "memory");
}
#endif // HAS_TCGEN05

// ---------------------------------------------------------------------------
// Kernel 1: fold conv into w0; write fp32 g_Weff (fallback) and pre-swizzled
// bf16 hi/lo blocks g_B (tcgen05 path). grid=HPAD, block=832.
// ---------------------------------------------------------------------------
__global__ void build_weff_kernel(const float* __restrict__ conv_w,
                                  const float* __restrict__ w0) {
    int j = blockIdx.x;      // hidden unit 0..255
    int p = threadIdx.x;     // k position 0..831
    float s = 0.0f;
    if (j < HID && p < KPIX) {
        int py = p / IMG, px = p % IMG;
        #pragma unroll
        for (int ky = 0; ky < 3; ky++)
            #pragma unroll
            for (int kx = 0; kx < 3; kx++) {
                int oy = py - ky, ox = px - kx;
                if (oy >= 0 && oy < OUT_HW && ox >= 0 && ox < OUT_HW)
                    s += conv_w[ky * 3 + kx] * w0[j * OPIX + oy * OUT_HW + ox];
            }
    }
    if (p < KPIX) g_Weff[j * KPIX + p] = s;

    __nv_bfloat16 hi = __float2bfloat16_rn(s);
    __nv_bfloat16 lo = __float2bfloat16_rn(s - __bfloat162float(hi));
    int chunk = p >> 6, kin = p & 63;
    uint32_t off = (uint32_t)(j * 128 + kin * 2);      // bytes within 32KB tile
    uint32_t sw  = off ^ ((off >> 3) & 0x70);          // SW128
    int base = chunk * (2 * HPAD * BK);                // 32768 elements / chunk
    g_B[base + (int)(sw >> 1)]             = hi;       // hi block
    g_B[base + HPAD * BK + (int)(sw >> 1)] = lo;       // lo block (+32KB)
}

// ---------------------------------------------------------------------------
// Kernel 2: fused  out = relu(X @ WeffT + b0) @ w1T + b1  (tcgen05, 2-way
// bf16 split). Warp-specialized: warp 0 = MMA issuer, warps 1-7 = loaders
// running 2 chunks ahead; B tiles arrive via cp.async.bulk.
// ---------------------------------------------------------------------------
// smem byte offsets
#define SM_CTRL   0          // tmem ptr @0; bfull @16/24; afull @32/40; mdone @48/56
#define SM_A      1024       // 2 stages x (hi 16KB | lo 16KB) = 65536
#define SM_B      66560      // 2 stages x (hi 32KB | lo 32KB) = 131072
#define SM_W1P    197632     // 256*5*8 = 10240
#define SM_B0     207872     // 1024
#define SM_OUT    208896     // 128*10*4 = 5120
#define SMEM_TOTAL 214016

__global__ void __launch_bounds__(GEMM_THREADS, 1)
gemm_fused_kernel(const float* __restrict__ X,
                  const float* __restrict__ b0,
                  const float* __restrict__ w1,
                  const float* __restrict__ b1,
                  float* __restrict__ out) {
#if HAS_TCGEN05
    extern __shared__ char smem[];
    const uint32_t smem_base = smem_to_u32(smem);
    const int tid = threadIdx.x;
    const int wid = tid >> 5;
    const int lid = tid & 31;
    const int m0  = blockIdx.x * BM;

    const uint32_t mb_bfull0 = smem_base + SM_CTRL + 16;
    const uint32_t mb_bfull1 = smem_base + SM_CTRL + 24;
    const uint32_t mb_afull0 = smem_base + SM_CTRL + 32;
    const uint32_t mb_afull1 = smem_base + SM_CTRL + 40;
    const uint32_t mb_mdone0 = smem_base + SM_CTRL + 48;
    const uint32_t mb_mdone1 = smem_base + SM_CTRL + 56;

    // TMEM alloc (warp 0, collective): 256 fp32 accumulator columns
    if (wid == 0) TCGEN05_ALLOC(smem_base + SM_CTRL, 256);

    // epilogue weights into smem + mbarrier init
    if (tid < HPAD) {
        int j = tid;
        float* b0s = (float*)(smem + SM_B0);
        b0s[j] = (j < HID) ? b0[j] : 0.0f;
        unsigned long long* w1p = (unsigned long long*)(smem + SM_W1P);
        #pragma unroll
        for (int cc = 0; cc < 5; cc++) {
            float a  = (j < HID) ? w1[(2 * cc) * HID + j] : 0.0f;
            float bb = (j < HID) ? w1[(2 * cc + 1) * HID + j] : 0.0f;
            w1p[j * 5 + cc] = pack2(a, bb);
        }
    }
    if (tid == 0) {
        MBARRIER_INIT(mb_bfull0, 1);
        MBARRIER_INIT(mb_bfull1, 1);
        MBARRIER_INIT(mb_afull0, NLOAD);
        MBARRIER_INIT(mb_afull1, NLOAD);
        MBARRIER_INIT(mb_mdone0, 1);
        MBARRIER_INIT(mb_mdone1, 1);
    }
    __syncthreads();

    uint32_t tmem;
    asm volatile("ld.shared.b32 %0, [%1];" : "=r"(tmem) : "r"(smem_base + SM_CTRL));

    if (wid == 0) {
        // =================== MMA issuer (warp 0) ===================
        int phA0 = 0, phA1 = 0, phB0 = 0, phB1 = 0;
        for (int c = 0; c < NCHUNK; c++) {
            const int b = c & 1;
            if (b == 0) {
                MBARRIER_WAIT_PARITY(mb_afull0, phA0); phA0 ^= 1;
                MBARRIER_WAIT_PARITY(mb_bfull0, phB0); phB0 ^= 1;
            } else {
                MBARRIER_WAIT_PARITY(mb_afull1, phA1); phA1 ^= 1;
                MBARRIER_WAIT_PARITY(mb_bfull1, phB1); phB1 ^= 1;
            }
            if (elect_one_pred()) {
                TCGEN05_FENCE_AFTER();
                uint64_t ah = MAKE_SMEM_DESC(smem_base + SM_A + b * 32768);
                uint64_t al = MAKE_SMEM_DESC(smem_base + SM_A + b * 32768 + 16384);
                uint64_t bh = MAKE_SMEM_DESC(smem_base + SM_B + b * 65536);
                uint64_t bl = MAKE_SMEM_DESC(smem_base + SM_B + b * 65536 + 32768);
                int nst = (c == NCHUNK - 1) ? 1 : 4;   // K=16 per MMA step
                for (int ks = 0; ks < nst; ks++) {
                    uint64_t o = (uint64_t)(ks * 2);   // +32B per 16 bf16
                    mma_f16_ss(tmem, ah + o, bh + o, MMA_IDESC, !(c == 0 && ks == 0));
                    mma_f16_ss(tmem, ah + o, bl + o, MMA_IDESC, true);
                    mma_f16_ss(tmem, al + o, bh + o, MMA_IDESC, true);
                }
                TCGEN05_COMMIT(b == 0 ? mb_mdone0 : mb_mdone1);
            }
        }
    } else {
        // ==================== loaders (warps 1-7) ====================
        const int ltid = tid - 32;   // 0..223

        auto load_a = [&](int c, int b) {
            const int kvalid = KPIX - c * BK;   // 64 except last chunk = 16
            char* ahi = smem + SM_A + b * 32768;
            char* alo = ahi + 16384;
            for (int idx = ltid; idx < BM * (BK / 4); idx += NLOAD) {
                int row  = idx >> 4;       // 0..127
                int col4 = idx & 15;       // float4 index within chunk
                if (col4 * 4 < kvalid) {
                    float4 v = *(const float4*)(
                        X + (long)(m0 + row) * KPIX + c * BK + col4 * 4);
                    __nv_bfloat16 h0 = __float2bfloat16_rn(v.x);
                    __nv_bfloat16 h1 = __float2bfloat16_rn(v.y);
                    __nv_bfloat16 h2 = __float2bfloat16_rn(v.z);
                    __nv_bfloat16 h3 = __float2bfloat16_rn(v.w);
                    __nv_bfloat16 l0 = __float2bfloat16_rn(v.x - __bfloat162float(h0));
                    __nv_bfloat16 l1 = __float2bfloat16_rn(v.y - __bfloat162float(h1));
                    __nv_bfloat16 l2 = __float2bfloat16_rn(v.z - __bfloat162float(h2));
                    __nv_bfloat16 l3 = __float2bfloat16_rn(v.w - __bfloat162float(h3));
                    __nv_bfloat162 hp0{h0, h1}, hp1{h2, h3};
                    __nv_bfloat162 lp0{l0, l1}, lp1{l2, l3};
                    uint2 hv, lv;
                    hv.x = *(uint32_t*)&hp0; hv.y = *(uint32_t*)&hp1;
                    lv.x = *(uint32_t*)&lp0; lv.y = *(uint32_t*)&lp1;
                    uint32_t off = (uint32_t)(row * 128 + col4 * 8);
                    uint32_t sw  = off ^ ((off >> 3) & 0x70);
                    *(uint2*)(ahi + sw) = hv;
                    *(uint2*)(alo + sw) = lv;
                }
            }
        };

        // prologue: fill both stages (chunks 0 and 1)
        if (tid == 32) {
            MBARRIER_EXPECT_TX(mb_bfull0, 65536);
            CP_ASYNC_BULK_G2S(smem_base + SM_B, (const void*)g_B, 65536, mb_bfull0);
            MBARRIER_EXPECT_TX(mb_bfull1, 65536);
            CP_ASYNC_BULK_G2S(smem_base + SM_B + 65536,
                              (const void*)(g_B + 2 * HPAD * BK), 65536, mb_bfull1);
        }
        load_a(0, 0);
        load_a(1, 1);
        FENCE_PROXY_ASYNC();
        MBARRIER_ARRIVE(mb_afull0);
        MBARRIER_ARRIVE(mb_afull1);

        // main loop: load chunk cl into stage cl&1 once MMA(cl-2) is done
        int phM0 = 0, phM1 = 0;
        for (int cl = 2; cl < NCHUNK; cl++) {
            const int b = cl & 1;
            if (b == 0) { MBARRIER_WAIT_PARITY(mb_mdone0, phM0); phM0 ^= 1; }
            else        { MBARRIER_WAIT_PARITY(mb_mdone1, phM1); phM1 ^= 1; }
            if (tid == 32) {
                uint32_t mb = (b == 0) ? mb_bfull0 : mb_bfull1;
                MBARRIER_EXPECT_TX(mb, 65536);
                CP_ASYNC_BULK_G2S(smem_base + SM_B + b * 65536,
                                  (const void*)(g_B + cl * 2 * HPAD * BK),
                                  65536, mb);
            }
            load_a(cl, b);
            FENCE_PROXY_ASYNC();
            MBARRIER_ARRIVE(b == 0 ? mb_afull0 : mb_afull1);
        }
    }

    // ---- all threads: wait for the final two MMA batches ----
    // mdone0: 7 commits (c=0,2,..,12) -> final completion parity 0
    // mdone1: 6 commits (c=1,3,..,11) -> final completion parity 1
    MBARRIER_WAIT_PARITY(mb_mdone0, 0);
    MBARRIER_WAIT_PARITY(mb_mdone1, 1);
    __syncthreads();
    TCGEN05_FENCE_AFTER();

    // ---- fused epilogue: h = relu(D + b0); out = h @ w1T + b1 ----
    const int sub  = wid & 3;          // TMEM subpartition (rows sub*32..+31)
    const int half = wid >> 2;         // 0: cols 0..127, 1: cols 128..255
    const int r    = sub * 32 + lid;
    const float* b0s = (const float*)(smem + SM_B0);
    const unsigned long long* w1p = (const unsigned long long*)(smem + SM_W1P);

    unsigned long long p2[5] = {0, 0, 0, 0, 0};
    #pragma unroll
    for (int blk = 0; blk < 4; blk++) {
        uint32_t d[32];
        TCGEN05_LD_32X32B_X32(d, tmem + half * 128 + blk * 32);
        TCGEN05_WAIT_LD();
        #pragma unroll
        for (int i = 0; i < 32; i++) {
            int j = half * 128 + blk * 32 + i;
            float h = fmaxf(__uint_as_float(d[i]) + b0s[j], 0.0f);
            unsigned long long hh = pack2(h, h);
            #pragma unroll
            for (int cc = 0; cc < 5; cc++) fma2(p2[cc], hh, w1p[j * 5 + cc]);
        }
    }
    TCGEN05_FENCE_BEFORE();

    float* outst = (float*)(smem + SM_OUT);
    if (half == 0) {
        #pragma unroll
        for (int cc = 0; cc < 5; cc++) {
            float2 f = unpack2(p2[cc]);
            outst[r * 10 + 2 * cc]     = f.x;
            outst[r * 10 + 2 * cc + 1] = f.y;
        }
    }
    __syncthreads();
    if (half == 1) {
        long m = m0 + r;
        #pragma unroll
        for (int cc = 0; cc < 5; cc++) {
            float2 f = unpack2(p2[cc]);
            out[m * NOUT + 2 * cc]     = outst[r * 10 + 2 * cc]     + f.x + b1[2 * cc];
            out[m * NOUT + 2 * cc + 1] = outst[r * 10 + 2 * cc + 1] + f.y + b1[2 * cc + 1];
        }
    }
    __syncthreads();

    if (wid == 0) {
        TCGEN05_RELINQUISH();
        TCGEN05_DEALLOC(tmem, 256);
    }

#else  // ---------------- portable fallback (non-sm_103a passes) ------------
    extern __shared__ char smem[];
    const int tid  = threadIdx.x;
    const int r    = tid & 127;
    const int half = tid >> 7;
    const int m0   = blockIdx.x * BM;
    float* hbuf = (float*)smem;

    const float* xr = X + (long)(m0 + r) * KPIX;
    for (int j = half * 100; j < half * 100 + 100; j++) {
        const float* wr = g_Weff + j * KPIX;
        float s = 0.0f;
        for (int k = 0; k < KPIX; k += 4) {
            float4 xv = *(const float4*)(xr + k);
            float4 wv = *(const float4*)(wr + k);
            s += xv.x * wv.x + xv.y * wv.y + xv.z * wv.z + xv.w * wv.w;
        }
        hbuf[r * HID + j] = fmaxf(s + b0[j], 0.0f);
    }
    __syncthreads();
    if (half == 0) {
        float o[NOUT];
        #pragma unroll
        for (int c = 0; c < NOUT; c++) o[c] = b1[c];
        for (int j = 0; j < HID; j++) {
            float h = hbuf[r * HID + j];
            #pragma unroll
            for (int c = 0; c < NOUT; c++) o[c] += h * w1[c * HID + j];
        }
        #pragma unroll
        for (int c = 0; c < NOUT; c++) out[(long)(m0 + r) * NOUT + c] = o[c];
    }
#endif
}

// ---------------------------------------------------------------------------
// kernel_launch: graph-capturable, allocation-free.
// Inputs (metadata order): x, conv_w, w0, b0, w1, b1
// ---------------------------------------------------------------------------
extern "C" void kernel_launch(void* const* d_in, const int* in_sizes, int n_in,
                              void* d_out, int out_size) {
    const float* x      = (const float*)d_in[0];
    const float* conv_w = (const float*)d_in[1];
    const float* w0     = (const float*)d_in[2];
    const float* b0     = (const float*)d_in[3];
    const float* w1     = (const float*)d_in[4];
    const float* b1     = (const float*)d_in[5];
    float* out = (float*)d_out;

    cudaFuncSetAttribute(gemm_fused_kernel,
                         cudaFuncAttributeMaxDynamicSharedMemorySize, SMEM_TOTAL);

    build_weff_kernel<<<HPAD, NCHUNK * BK>>>(conv_w, w0);
    gemm_fused_kernel<<<BATCH / BM, GEMM_THREADS, SMEM_TOTAL>>>(x, b0, w1, b1, out);
}

// round 7
// speedup vs baseline: 6.4972x; 2.0507x over previous
#include <cuda_runtime.h>
#include <cuda_bf16.h>
#include <cstdint>

// ---------------------------------------------------------------------------
// Problem constants
// ---------------------------------------------------------------------------
#define BATCH   32768
#define IMG     28
#define KPIX    784      // GEMM K
#define OUT_HW  26
#define OPIX    676
#define HID     200
#define HPAD    256      // padded hidden (GEMM N)
#define NOUT    10

#define BM      128      // M rows per CTA
#define BK      64       // K per chunk (bf16 -> 128B rows, SW128)
#define NCHUNK  13       // 12*64 + 16
#define GEMM_THREADS 256
#define NLOAD   224      // loader threads (warps 1..7)
#define NF4     (BM * (BK / 4))   // 2048 float4 per chunk
#define LPT     10                // max float4 per loader thread

// idesc kind::f16 (bf16 in, fp32 acc), M=128, N=256
#define MMA_IDESC 0x8400490u

#if defined(__CUDA_ARCH__) && defined(__CUDA_ARCH_FEAT_SM103_ALL)
#define HAS_TCGEN05 1
#else
#define HAS_TCGEN05 0
#endif

// ---------------------------------------------------------------------------
// Global scratch.
//  g_B   : per chunk, 64KB contiguous block = [hi 32KB | lo 32KB], SW128
//          pre-swizzled -> one cp.async.bulk per chunk
//  g_Weff: fp32 Weff for the portable fallback path (never runs on GB300)
// ---------------------------------------------------------------------------
__device__ __align__(16) __nv_bfloat16 g_B[NCHUNK * 2 * HPAD * BK];
__device__ __align__(16) float         g_Weff[HPAD * KPIX];

// ---------------------------------------------------------------------------
// Arch-neutral helpers
// ---------------------------------------------------------------------------
__device__ __forceinline__ uint32_t smem_to_u32(const void* p) {
    uint32_t a;
    asm("{ .reg .u64 t; cvta.to.shared.u64 t, %1; cvt.u32.u64 %0, t; }"
        : "=r"(a) : "l"(p));
    return a;
}
__device__ __forceinline__ unsigned long long pack2(float lo, float hi) {
    unsigned long long r;
    asm("mov.b64 %0, {%1, %2};" : "=l"(r) : "f"(lo), "f"(hi));
    return r;
}
__device__ __forceinline__ void fma2(unsigned long long& d,
                                     unsigned long long a,
                                     unsigned long long b) {
    asm("fma.rn.f32x2 %0, %1, %2, %0;" : "+l"(d) : "l"(a), "l"(b));
}
__device__ __forceinline__ float2 unpack2(unsigned long long v) {
    float2 f;
    asm("mov.b64 {%0, %1}, %2;" : "=f"(f.x), "=f"(f.y) : "l"(v));
    return f;
}

#if HAS_TCGEN05
// ---------------------------------------------------------------------------
// tcgen05 / mbarrier / bulk-copy PTX helpers (sm_103a-only compilation)
// ---------------------------------------------------------------------------
__device__ __forceinline__ uint32_t elect_one_pred() {
    uint32_t pred;
    asm volatile(
        "{\n\t.reg .pred p;\n\t"
        "elect.sync _|p, 0xFFFFFFFF;\n\t"
        "selp.b32 %0, 1, 0, p;\n\t}"
        : "=r"(pred));
    return pred;
}

#define MBARRIER_INIT(addr, cnt) \
    asm volatile("mbarrier.init.shared.b64 [%0], %1;" \
        :: "r"((uint32_t)(addr)), "r"((uint32_t)(cnt)) : "memory")

#define MBARRIER_ARRIVE(addr) \
    asm volatile("mbarrier.arrive.release.cta.shared::cta.b64 _, [%0];" \
        :: "r"((uint32_t)(addr)) : "memory")

#define MBARRIER_EXPECT_TX(addr, bytes) \
    asm volatile("mbarrier.arrive.expect_tx.shared.b64 _, [%0], %1;" \
        :: "r"((uint32_t)(addr)), "r"((uint32_t)(bytes)) : "memory")

#define MBARRIER_WAIT_PARITY(addr, par) do { \
    uint32_t _m = (uint32_t)(addr); \
    uint32_t _p = (uint32_t)(par); \
    uint32_t _done; \
    asm volatile( \
        "{\n\t.reg .pred p;\n\t" \
        "mbarrier.try_wait.parity.acquire.cta.shared::cta.b64 p, [%1], %2;\n\t" \
        "selp.b32 %0, 1, 0, p;\n\t}" \
        : "=r"(_done) : "r"(_m), "r"(_p) : "memory"); \
    if (!_done) { \
        asm volatile( \
            "{\n\t.reg .pred P1;\n\t" \
            "WAIT_LOOP_%=:\n\t" \
            "mbarrier.try_wait.parity.acquire.cta.shared::cta.b64 P1, [%0], %1, 0x989680;\n\t" \
            "@P1 bra.uni WAIT_DONE_%=;\n\t" \
            "bra.uni WAIT_LOOP_%=;\n\t" \
            "WAIT_DONE_%=:\n\t}" \
            :: "r"(_m), "r"(_p) : "memory"); \
    } \
} while (0)

// plain bulk copy gmem -> smem, completion via tx mbarrier (UBLKCP)
#define CP_ASYNC_BULK_G2S(dst, src, bytes, mbar) \
    asm volatile( \
        "cp.async.bulk.shared::cluster.global.mbarrier::complete_tx::bytes " \
        "[%0], [%1], %2, [%3];" \
        :: "r"((uint32_t)(dst)), "l"(src), "r"((uint32_t)(bytes)), \
           "r"((uint32_t)(mbar)) : "memory")

#define TCGEN05_ALLOC(res_addr, ncols) \
    asm volatile("tcgen05.alloc.cta_group::1.sync.aligned.shared::cta.b32 [%0], %1;" \
        :: "r"((uint32_t)(res_addr)), "r"((uint32_t)(ncols)) : "memory")
#define TCGEN05_DEALLOC(tmem, ncols) \
    asm volatile("tcgen05.dealloc.cta_group::1.sync.aligned.b32 %0, %1;" \
        :: "r"(tmem), "r"((uint32_t)(ncols)))
#define TCGEN05_RELINQUISH() \
    asm volatile("tcgen05.relinquish_alloc_permit.cta_group::1.sync.aligned;")
#define TCGEN05_COMMIT(mbar) \
    asm volatile("tcgen05.commit.cta_group::1.mbarrier::arrive::one.shared::cluster.b64 [%0];" \
        :: "r"((uint32_t)(mbar)) : "memory")
#define TCGEN05_WAIT_LD() \
    asm volatile("tcgen05.wait::ld.sync.aligned;" ::: "memory")
#define TCGEN05_FENCE_BEFORE() \
    asm volatile("tcgen05.fence::before_thread_sync;" ::: "memory")
#define TCGEN05_FENCE_AFTER() \
    asm volatile("tcgen05.fence::after_thread_sync;" ::: "memory")
#define FENCE_PROXY_ASYNC() \
    asm volatile("fence.proxy.async.shared::cta;" ::: "memory")

#define TCGEN05_LD_32X32B_X32(r, tmem_addr) \
    asm volatile( \
        "tcgen05.ld.sync.aligned.32x32b.x32.b32 " \
        "{%0, %1, %2, %3, %4, %5, %6, %7, " \
        " %8, %9, %10, %11, %12, %13, %14, %15, " \
        " %16, %17, %18, %19, %20, %21, %22, %23, " \
        " %24, %25, %26, %27, %28, %29, %30, %31}, [%32];" \
        : "=r"((r)[0]),  "=r"((r)[1]),  "=r"((r)[2]),  "=r"((r)[3]), \
          "=r"((r)[4]),  "=r"((r)[5]),  "=r"((r)[6]),  "=r"((r)[7]), \
          "=r"((r)[8]),  "=r"((r)[9]),  "=r"((r)[10]), "=r"((r)[11]), \
          "=r"((r)[12]), "=r"((r)[13]), "=r"((r)[14]), "=r"((r)[15]), \
          "=r"((r)[16]), "=r"((r)[17]), "=r"((r)[18]), "=r"((r)[19]), \
          "=r"((r)[20]), "=r"((r)[21]), "=r"((r)[22]), "=r"((r)[23]), \
          "=r"((r)[24]), "=r"((r)[25]), "=r"((r)[26]), "=r"((r)[27]), \
          "=r"((r)[28]), "=r"((r)[29]), "=r"((r)[30]), "=r"((r)[31]) \
        : "r"(tmem_addr))

// SW128 K-major descriptor base (LBO=1, SBO=64, version=1, layout=SW128)
static constexpr uint64_t SMEM_DESC_BASE_SW128 =
    (uint64_t(2)  << 61) | (uint64_t(1) << 46) |
    (uint64_t(64) << 32) | (uint64_t(1) << 16);
#define MAKE_SMEM_DESC(addr) \
    (SMEM_DESC_BASE_SW128 | ((uint64_t)((addr) >> 4) & 0x3FFF))

__device__ __forceinline__ void mma_f16_ss(uint32_t d_tmem, uint64_t a_desc,
                                           uint64_t b_desc, uint32_t idesc,
                                           bool acc) {
    uint32_t en = acc ? 1u : 0u;
    asm volatile(
        "{\n\t.reg .pred p;\n\t"
        "setp.ne.u32 p, %5, 0;\n\t"
        "tcgen05.mma.cta_group::1.kind::f16 [%0], %1, %2, %3, "
        "{%4, %4, %4, %4}, p;\n\t}"
        :: "r"(d_tmem), "l"(a_desc), "l"(b_desc), "r"(idesc),
           "r"(0u), "r"(en)
        : "memory");
}
#endif // HAS_TCGEN05

// ---------------------------------------------------------------------------
// Kernel 1: fold conv into w0; write fp32 g_Weff (fallback) and pre-swizzled
// bf16 hi/lo blocks g_B (tcgen05 path). grid=HPAD, block=832.
// ---------------------------------------------------------------------------
__global__ void build_weff_kernel(const float* __restrict__ conv_w,
                                  const float* __restrict__ w0) {
    int j = blockIdx.x;      // hidden unit 0..255
    int p = threadIdx.x;     // k position 0..831
    float s = 0.0f;
    if (j < HID && p < KPIX) {
        int py = p / IMG, px = p % IMG;
        #pragma unroll
        for (int ky = 0; ky < 3; ky++)
            #pragma unroll
            for (int kx = 0; kx < 3; kx++) {
                int oy = py - ky, ox = px - kx;
                if (oy >= 0 && oy < OUT_HW && ox >= 0 && ox < OUT_HW)
                    s += conv_w[ky * 3 + kx] * w0[j * OPIX + oy * OUT_HW + ox];
            }
    }
    if (p < KPIX) g_Weff[j * KPIX + p] = s;

    __nv_bfloat16 hi = __float2bfloat16_rn(s);
    __nv_bfloat16 lo = __float2bfloat16_rn(s - __bfloat162float(hi));
    int chunk = p >> 6, kin = p & 63;
    uint32_t off = (uint32_t)(j * 128 + kin * 2);      // bytes within 32KB tile
    uint32_t sw  = off ^ ((off >> 3) & 0x70);          // SW128
    int base = chunk * (2 * HPAD * BK);                // 32768 elements / chunk
    g_B[base + (int)(sw >> 1)]             = hi;       // hi block
    g_B[base + HPAD * BK + (int)(sw >> 1)] = lo;       // lo block (+32KB)
}

// ---------------------------------------------------------------------------
// Kernel 2: fused  out = relu(X @ WeffT + b0) @ w1T + b1  (tcgen05, 2-way
// bf16 split). Warp-specialized: warp 0 = MMA issuer, warps 1-7 = loaders.
// A-loader is two-phase (batch all LDGs, then convert+STS) for MLP ~10.
// ---------------------------------------------------------------------------
// smem byte offsets
#define SM_CTRL   0          // tmem ptr @0; bfull @16/24; afull @32/40; mdone @48/56
#define SM_A      1024       // 2 stages x (hi 16KB | lo 16KB) = 65536
#define SM_B      66560      // 2 stages x (hi 32KB | lo 32KB) = 131072
#define SM_W1P    197632     // 256*5*8 = 10240
#define SM_B0     207872     // 1024
#define SM_OUT    208896     // 128*10*4 = 5120
#define SMEM_TOTAL 214016

__global__ void __launch_bounds__(GEMM_THREADS, 1)
gemm_fused_kernel(const float* __restrict__ X,
                  const float* __restrict__ b0,
                  const float* __restrict__ w1,
                  const float* __restrict__ b1,
                  float* __restrict__ out) {
#if HAS_TCGEN05
    extern __shared__ char smem[];
    const uint32_t smem_base = smem_to_u32(smem);
    const int tid = threadIdx.x;
    const int wid = tid >> 5;
    const int lid = tid & 31;
    const int m0  = blockIdx.x * BM;

    const uint32_t mb_bfull0 = smem_base + SM_CTRL + 16;
    const uint32_t mb_bfull1 = smem_base + SM_CTRL + 24;
    const uint32_t mb_afull0 = smem_base + SM_CTRL + 32;
    const uint32_t mb_afull1 = smem_base + SM_CTRL + 40;
    const uint32_t mb_mdone0 = smem_base + SM_CTRL + 48;
    const uint32_t mb_mdone1 = smem_base + SM_CTRL + 56;

    // TMEM alloc (warp 0, collective): 256 fp32 accumulator columns
    if (wid == 0) TCGEN05_ALLOC(smem_base + SM_CTRL, 256);

    // epilogue weights into smem + mbarrier init
    if (tid < HPAD) {
        int j = tid;
        float* b0s = (float*)(smem + SM_B0);
        b0s[j] = (j < HID) ? b0[j] : 0.0f;
        unsigned long long* w1p = (unsigned long long*)(smem + SM_W1P);
        #pragma unroll
        for (int cc = 0; cc < 5; cc++) {
            float a  = (j < HID) ? w1[(2 * cc) * HID + j] : 0.0f;
            float bb = (j < HID) ? w1[(2 * cc + 1) * HID + j] : 0.0f;
            w1p[j * 5 + cc] = pack2(a, bb);
        }
    }
    if (tid == 0) {
        MBARRIER_INIT(mb_bfull0, 1);
        MBARRIER_INIT(mb_bfull1, 1);
        MBARRIER_INIT(mb_afull0, NLOAD);
        MBARRIER_INIT(mb_afull1, NLOAD);
        MBARRIER_INIT(mb_mdone0, 1);
        MBARRIER_INIT(mb_mdone1, 1);
    }
    __syncthreads();

    uint32_t tmem;
    asm volatile("ld.shared.b32 %0, [%1];" : "=r"(tmem) : "r"(smem_base + SM_CTRL));

    if (wid == 0) {
        // =================== MMA issuer (warp 0) ===================
        int phA0 = 0, phA1 = 0, phB0 = 0, phB1 = 0;
        for (int c = 0; c < NCHUNK; c++) {
            const int b = c & 1;
            if (b == 0) {
                MBARRIER_WAIT_PARITY(mb_afull0, phA0); phA0 ^= 1;
                MBARRIER_WAIT_PARITY(mb_bfull0, phB0); phB0 ^= 1;
            } else {
                MBARRIER_WAIT_PARITY(mb_afull1, phA1); phA1 ^= 1;
                MBARRIER_WAIT_PARITY(mb_bfull1, phB1); phB1 ^= 1;
            }
            if (elect_one_pred()) {
                TCGEN05_FENCE_AFTER();
                uint64_t ah = MAKE_SMEM_DESC(smem_base + SM_A + b * 32768);
                uint64_t al = MAKE_SMEM_DESC(smem_base + SM_A + b * 32768 + 16384);
                uint64_t bh = MAKE_SMEM_DESC(smem_base + SM_B + b * 65536);
                uint64_t bl = MAKE_SMEM_DESC(smem_base + SM_B + b * 65536 + 32768);
                int nst = (c == NCHUNK - 1) ? 1 : 4;   // K=16 per MMA step
                for (int ks = 0; ks < nst; ks++) {
                    uint64_t o = (uint64_t)(ks * 2);   // +32B per 16 bf16
                    mma_f16_ss(tmem, ah + o, bh + o, MMA_IDESC, !(c == 0 && ks == 0));
                    mma_f16_ss(tmem, ah + o, bl + o, MMA_IDESC, true);
                    mma_f16_ss(tmem, al + o, bh + o, MMA_IDESC, true);
                }
                TCGEN05_COMMIT(b == 0 ? mb_mdone0 : mb_mdone1);
            }
        }
    } else {
        // ==================== loaders (warps 1-7) ====================
        const int ltid = tid - 32;   // 0..223

        // Two-phase loader: batch ALL global loads first (MLP ~= LPT), then
        // convert + swizzled STS. This is the R6 fix: MLP 1 -> 10.
        auto load_a = [&](int c, int b) {
            const int kvalid = KPIX - c * BK;   // 64 except last chunk = 16
            char* ahi = smem + SM_A + b * 32768;
            char* alo = ahi + 16384;

            float4 v[LPT];
            #pragma unroll
            for (int i = 0; i < LPT; i++) {
                int idx  = ltid + i * NLOAD;
                int row  = idx >> 4;
                int col4 = idx & 15;
                if (idx < NF4 && col4 * 4 < kvalid) {
                    v[i] = *(const float4*)(
                        X + (long)(m0 + row) * KPIX + c * BK + col4 * 4);
                }
            }
            #pragma unroll
            for (int i = 0; i < LPT; i++) {
                int idx  = ltid + i * NLOAD;
                int row  = idx >> 4;
                int col4 = idx & 15;
                if (idx < NF4 && col4 * 4 < kvalid) {
                    __nv_bfloat16 h0 = __float2bfloat16_rn(v[i].x);
                    __nv_bfloat16 h1 = __float2bfloat16_rn(v[i].y);
                    __nv_bfloat16 h2 = __float2bfloat16_rn(v[i].z);
                    __nv_bfloat16 h3 = __float2bfloat16_rn(v[i].w);
                    __nv_bfloat16 l0 = __float2bfloat16_rn(v[i].x - __bfloat162float(h0));
                    __nv_bfloat16 l1 = __float2bfloat16_rn(v[i].y - __bfloat162float(h1));
                    __nv_bfloat16 l2 = __float2bfloat16_rn(v[i].z - __bfloat162float(h2));
                    __nv_bfloat16 l3 = __float2bfloat16_rn(v[i].w - __bfloat162float(h3));
                    __nv_bfloat162 hp0{h0, h1}, hp1{h2, h3};
                    __nv_bfloat162 lp0{l0, l1}, lp1{l2, l3};
                    uint2 hv, lv;
                    hv.x = *(uint32_t*)&hp0; hv.y = *(uint32_t*)&hp1;
                    lv.x = *(uint32_t*)&lp0; lv.y = *(uint32_t*)&lp1;
                    uint32_t off = (uint32_t)(row * 128 + col4 * 8);
                    uint32_t sw  = off ^ ((off >> 3) & 0x70);
                    *(uint2*)(ahi + sw) = hv;
                    *(uint2*)(alo + sw) = lv;
                }
            }
        };

        // prologue: fill both stages (chunks 0 and 1)
        if (tid == 32) {
            MBARRIER_EXPECT_TX(mb_bfull0, 65536);
            CP_ASYNC_BULK_G2S(smem_base + SM_B, (const void*)g_B, 65536, mb_bfull0);
            MBARRIER_EXPECT_TX(mb_bfull1, 65536);
            CP_ASYNC_BULK_G2S(smem_base + SM_B + 65536,
                              (const void*)(g_B + 2 * HPAD * BK), 65536, mb_bfull1);
        }
        load_a(0, 0);
        load_a(1, 1);
        FENCE_PROXY_ASYNC();
        MBARRIER_ARRIVE(mb_afull0);
        MBARRIER_ARRIVE(mb_afull1);

        // main loop: load chunk cl into stage cl&1 once MMA(cl-2) is done
        int phM0 = 0, phM1 = 0;
        for (int cl = 2; cl < NCHUNK; cl++) {
            const int b = cl & 1;
            if (b == 0) { MBARRIER_WAIT_PARITY(mb_mdone0, phM0); phM0 ^= 1; }
            else        { MBARRIER_WAIT_PARITY(mb_mdone1, phM1); phM1 ^= 1; }
            if (tid == 32) {
                uint32_t mb = (b == 0) ? mb_bfull0 : mb_bfull1;
                MBARRIER_EXPECT_TX(mb, 65536);
                CP_ASYNC_BULK_G2S(smem_base + SM_B + b * 65536,
                                  (const void*)(g_B + cl * 2 * HPAD * BK),
                                  65536, mb);
            }
            load_a(cl, b);
            FENCE_PROXY_ASYNC();
            MBARRIER_ARRIVE(b == 0 ? mb_afull0 : mb_afull1);
        }
    }

    // ---- all threads: wait for the final two MMA batches ----
    // mdone0: 7 commits (c=0,2,..,12) -> final completion parity 0
    // mdone1: 6 commits (c=1,3,..,11) -> final completion parity 1
    MBARRIER_WAIT_PARITY(mb_mdone0, 0);
    MBARRIER_WAIT_PARITY(mb_mdone1, 1);
    __syncthreads();
    TCGEN05_FENCE_AFTER();

    // ---- fused epilogue: h = relu(D + b0); out = h @ w1T + b1 ----
    const int sub  = wid & 3;          // TMEM subpartition (rows sub*32..+31)
    const int half = wid >> 2;         // 0: cols 0..127, 1: cols 128..255
    const int r    = sub * 32 + lid;
    const float* b0s = (const float*)(smem + SM_B0);
    const unsigned long long* w1p = (const unsigned long long*)(smem + SM_W1P);

    unsigned long long p2[5] = {0, 0, 0, 0, 0};
    #pragma unroll
    for (int blk = 0; blk < 4; blk++) {
        uint32_t d[32];
        TCGEN05_LD_32X32B_X32(d, tmem + half * 128 + blk * 32);
        TCGEN05_WAIT_LD();
        #pragma unroll
        for (int i = 0; i < 32; i++) {
            int j = half * 128 + blk * 32 + i;
            float h = fmaxf(__uint_as_float(d[i]) + b0s[j], 0.0f);
            unsigned long long hh = pack2(h, h);
            #pragma unroll
            for (int cc = 0; cc < 5; cc++) fma2(p2[cc], hh, w1p[j * 5 + cc]);
        }
    }
    TCGEN05_FENCE_BEFORE();

    float* outst = (float*)(smem + SM_OUT);
    if (half == 0) {
        #pragma unroll
        for (int cc = 0; cc < 5; cc++) {
            float2 f = unpack2(p2[cc]);
            outst[r * 10 + 2 * cc]     = f.x;
            outst[r * 10 + 2 * cc + 1] = f.y;
        }
    }
    __syncthreads();
    if (half == 1) {
        long m = m0 + r;
        #pragma unroll
        for (int cc = 0; cc < 5; cc++) {
            float2 f = unpack2(p2[cc]);
            out[m * NOUT + 2 * cc]     = outst[r * 10 + 2 * cc]     + f.x + b1[2 * cc];
            out[m * NOUT + 2 * cc + 1] = outst[r * 10 + 2 * cc + 1] + f.y + b1[2 * cc + 1];
        }
    }
    __syncthreads();

    if (wid == 0) {
        TCGEN05_RELINQUISH();
        TCGEN05_DEALLOC(tmem, 256);
    }

#else  // ---------------- portable fallback (non-sm_103a passes) ------------
    extern __shared__ char smem[];
    const int tid  = threadIdx.x;
    const int r    = tid & 127;
    const int half = tid >> 7;
    const int m0   = blockIdx.x * BM;
    float* hbuf = (float*)smem;

    const float* xr = X + (long)(m0 + r) * KPIX;
    for (int j = half * 100; j < half * 100 + 100; j++) {
        const float* wr = g_Weff + j * KPIX;
        float s = 0.0f;
        for (int k = 0; k < KPIX; k += 4) {
            float4 xv = *(const float4*)(xr + k);
            float4 wv = *(const float4*)(wr + k);
            s += xv.x * wv.x + xv.y * wv.y + xv.z * wv.z + xv.w * wv.w;
        }
        hbuf[r * HID + j] = fmaxf(s + b0[j], 0.0f);
    }
    __syncthreads();
    if (half == 0) {
        float o[NOUT];
        #pragma unroll
        for (int c = 0; c < NOUT; c++) o[c] = b1[c];
        for (int j = 0; j < HID; j++) {
            float h = hbuf[r * HID + j];
            #pragma unroll
            for (int c = 0; c < NOUT; c++) o[c] += h * w1[c * HID + j];
        }
        #pragma unroll
        for (int c = 0; c < NOUT; c++) out[(long)(m0 + r) * NOUT + c] = o[c];
    }
#endif
}

// ---------------------------------------------------------------------------
// kernel_launch: graph-capturable, allocation-free.
// Inputs (metadata order): x, conv_w, w0, b0, w1, b1
// ---------------------------------------------------------------------------
extern "C" void kernel_launch(void* const* d_in, const int* in_sizes, int n_in,
                              void* d_out, int out_size) {
    const float* x      = (const float*)d_in[0];
    const float* conv_w = (const float*)d_in[1];
    const float* w0     = (const float*)d_in[2];
    const float* b0     = (const float*)d_in[3];
    const float* w1     = (const float*)d_in[4];
    const float* b1     = (const float*)d_in[5];
    float* out = (float*)d_out;

    cudaFuncSetAttribute(gemm_fused_kernel,
                         cudaFuncAttributeMaxDynamicSharedMemorySize, SMEM_TOTAL);

    build_weff_kernel<<<HPAD, NCHUNK * BK>>>(conv_w, w0);
    gemm_fused_kernel<<<BATCH / BM, GEMM_THREADS, SMEM_TOTAL>>>(x, b0, w1, b1, out);
}